// round 15
// baseline (speedup 1.0000x reference)
#include <cuda_runtime.h>

// IMU preintegration (RmiModel). Associative segment composition:
//   segment = (Q, p, r, tau);
//   compose: Q=Q1Q2, p=p1+Q1 p2, r=r1+tau2 p1+Q1 r2, tau=tau1+tau2.
// 4 warps per batch (block = 128 thr = 1 batch). Each lane integrates 8
// contiguous steps as TWO chains of 4 steps PACKED into f32x2 (A=.lo, B=.hi),
// one scalar compose merges A∘B. For the T<=1025 fast path (rounds==1):
// only 2 shfl tree stages per warp (lane l -> ordered segment [8l,8l+32)),
// lanes 0,4,..,28 dump 8 segments/warp to smem (32 ordered segments/block),
// and warp 0 alone finishes with one 5-stage ordered tree + output. This
// removes 3 of 5 tree stages (213 instr) from every hot lane at the cost of
// one per-block final tree. Generic rounds>1 path keeps the full tree.

typedef unsigned long long u64;

__device__ __forceinline__ u64 pk2(float lo, float hi) {
    u64 r;
    asm("mov.b64 %0, {%1, %2};" : "=l"(r)
        : "r"(__float_as_uint(lo)), "r"(__float_as_uint(hi)));
    return r;
}
__device__ __forceinline__ void up2(u64 v, float& lo, float& hi) {
    unsigned int a, b;
    asm("mov.b64 {%0, %1}, %2;" : "=r"(a), "=r"(b) : "l"(v));
    lo = __uint_as_float(a); hi = __uint_as_float(b);
}
__device__ __forceinline__ u64 dup2(float c) { return pk2(c, c); }
__device__ __forceinline__ u64 f2fma(u64 a, u64 b, u64 c) {
    u64 d; asm("fma.rn.f32x2 %0, %1, %2, %3;" : "=l"(d) : "l"(a), "l"(b), "l"(c)); return d;
}
__device__ __forceinline__ u64 f2mul(u64 a, u64 b) {
    u64 d; asm("mul.rn.f32x2 %0, %1, %2;" : "=l"(d) : "l"(a), "l"(b)); return d;
}
__device__ __forceinline__ u64 f2add(u64 a, u64 b) {
    u64 d; asm("add.rn.f32x2 %0, %1, %2;" : "=l"(d) : "l"(a), "l"(b)); return d;
}
__device__ __forceinline__ u64 f2neg(u64 a) { return a ^ 0x8000000080000000ULL; }

// Packed so3 exponential, PURE TAYLOR (validity deferred via acc += t2).
__device__ __forceinline__ void pso3_R(u64 px, u64 py, u64 pz, u64 R[9], u64& acc) {
    u64 px2 = f2mul(px, px), py2 = f2mul(py, py), pz2 = f2mul(pz, pz);
    u64 syz = f2add(py2, pz2), sxz = f2add(px2, pz2), sxy = f2add(px2, py2);
    u64 t2  = f2add(px2, syz);
    acc = f2add(acc, t2);
    const u64 ONE = dup2(1.0f);
    u64 A  = f2fma(t2, dup2(1.0f/120.0f), dup2(-1.0f/6.0f));
    A      = f2fma(t2, A, ONE);
    u64 Bc = f2fma(t2, dup2(1.0f/720.0f), dup2(-1.0f/24.0f));
    Bc     = f2fma(t2, Bc, dup2(0.5f));

    u64 nBc = f2neg(Bc);
    u64 An  = f2neg(A);
    R[0] = f2fma(nBc, syz, ONE);
    R[4] = f2fma(nBc, sxz, ONE);
    R[8] = f2fma(nBc, sxy, ONE);
    u64 Bxy = f2mul(Bc, f2mul(px, py));
    u64 Bxz = f2mul(Bc, f2mul(px, pz));
    u64 Byz = f2mul(Bc, f2mul(py, pz));
    R[3] = f2fma(A,  pz, Bxy);
    R[1] = f2fma(An, pz, Bxy);
    R[2] = f2fma(A,  py, Bxz);
    R[6] = f2fma(An, py, Bxz);
    R[7] = f2fma(A,  px, Byz);
    R[5] = f2fma(An, px, Byz);
}

__device__ __forceinline__ void pstep0(u64 Q[9], u64 p[3], u64 r[3], u64& tau,
                                       u64 dt, u64 aX, u64 aY, u64 aZ,
                                       u64 wX, u64 wY, u64 wZ, u64& acc) {
    u64 hdt2 = f2mul(dup2(0.5f), f2mul(dt, dt));
    r[0] = f2mul(aX, hdt2); r[1] = f2mul(aY, hdt2); r[2] = f2mul(aZ, hdt2);
    p[0] = f2mul(aX, dt);   p[1] = f2mul(aY, dt);   p[2] = f2mul(aZ, dt);
    tau  = dt;
    pso3_R(f2mul(wX, dt), f2mul(wY, dt), f2mul(wZ, dt), Q, acc);
}

__device__ __forceinline__ void pstep(u64 Q[9], u64 p[3], u64 r[3], u64& tau,
                                      u64 dt, u64 aX, u64 aY, u64 aZ,
                                      u64 wX, u64 wY, u64 wZ, u64& acc) {
    u64 ca0 = f2fma(Q[0], aX, f2fma(Q[1], aY, f2mul(Q[2], aZ)));
    u64 ca1 = f2fma(Q[3], aX, f2fma(Q[4], aY, f2mul(Q[5], aZ)));
    u64 ca2 = f2fma(Q[6], aX, f2fma(Q[7], aY, f2mul(Q[8], aZ)));
    u64 hdt2 = f2mul(dup2(0.5f), f2mul(dt, dt));
    r[0] = f2fma(p[0], dt, f2fma(ca0, hdt2, r[0]));
    r[1] = f2fma(p[1], dt, f2fma(ca1, hdt2, r[1]));
    r[2] = f2fma(p[2], dt, f2fma(ca2, hdt2, r[2]));
    p[0] = f2fma(ca0, dt, p[0]);
    p[1] = f2fma(ca1, dt, p[1]);
    p[2] = f2fma(ca2, dt, p[2]);
    tau  = f2add(tau, dt);

    u64 R[9];
    pso3_R(f2mul(wX, dt), f2mul(wY, dt), f2mul(wZ, dt), R, acc);

    u64 n0 = f2fma(Q[0], R[0], f2fma(Q[1], R[3], f2mul(Q[2], R[6])));
    u64 n1 = f2fma(Q[0], R[1], f2fma(Q[1], R[4], f2mul(Q[2], R[7])));
    u64 n2 = f2fma(Q[0], R[2], f2fma(Q[1], R[5], f2mul(Q[2], R[8])));
    u64 n3 = f2fma(Q[3], R[0], f2fma(Q[4], R[3], f2mul(Q[5], R[6])));
    u64 n4 = f2fma(Q[3], R[1], f2fma(Q[4], R[4], f2mul(Q[5], R[7])));
    u64 n5 = f2fma(Q[3], R[2], f2fma(Q[4], R[5], f2mul(Q[5], R[8])));
    u64 n6 = f2fma(Q[6], R[0], f2fma(Q[7], R[3], f2mul(Q[8], R[6])));
    u64 n7 = f2fma(Q[6], R[1], f2fma(Q[7], R[4], f2mul(Q[8], R[7])));
    u64 n8 = f2fma(Q[6], R[2], f2fma(Q[7], R[5], f2mul(Q[8], R[8])));
    Q[0]=n0; Q[1]=n1; Q[2]=n2;
    Q[3]=n3; Q[4]=n4; Q[5]=n5;
    Q[6]=n6; Q[7]=n7; Q[8]=n8;
}

// Scalar compose: T1 <- T1 ∘ T2
__device__ __forceinline__ void compose(float Q1[9], float p1[3], float r1[3], float& tau1,
                                        const float Q2[9], const float p2[3],
                                        const float r2[3], float tau2) {
    float nQ[9];
    #pragma unroll
    for (int i = 0; i < 3; i++) {
        #pragma unroll
        for (int j = 0; j < 3; j++)
            nQ[3*i+j] = Q1[3*i+0]*Q2[0+j] + Q1[3*i+1]*Q2[3+j] + Q1[3*i+2]*Q2[6+j];
    }
    float np[3], nr[3];
    #pragma unroll
    for (int i = 0; i < 3; i++) {
        float Qp = Q1[3*i+0]*p2[0] + Q1[3*i+1]*p2[1] + Q1[3*i+2]*p2[2];
        float Qr = Q1[3*i+0]*r2[0] + Q1[3*i+1]*r2[1] + Q1[3*i+2]*r2[2];
        np[i] = p1[i] + Qp;
        nr[i] = r1[i] + tau2 * p1[i] + Qr;
    }
    #pragma unroll
    for (int i = 0; i < 9; i++) Q1[i] = nQ[i];
    #pragma unroll
    for (int i = 0; i < 3; i++) { p1[i] = np[i]; r1[i] = nr[i]; }
    tau1 += tau2;
}

// One ordered shfl tree stage: combine [lane..] with [lane+off..].
__device__ __forceinline__ void tree_stage(float Q[9], float p[3], float r[3], float& tau,
                                           int off) {
    float Q2[9], p2[3], r2[3], tau2;
    #pragma unroll
    for (int i = 0; i < 9; i++) Q2[i] = __shfl_down_sync(0xffffffffu, Q[i], off);
    #pragma unroll
    for (int i = 0; i < 3; i++) p2[i] = __shfl_down_sync(0xffffffffu, p[i], off);
    #pragma unroll
    for (int i = 0; i < 3; i++) r2[i] = __shfl_down_sync(0xffffffffu, r[i], off);
    tau2 = __shfl_down_sync(0xffffffffu, tau, off);
    compose(Q, p, r, tau, Q2, p2, r2, tau2);
}

// ---------- COLD exact path (never taken on this data) ----------
__device__ void exact_chain4(const float* __restrict__ xb, int kk, int T, int nsteps,
                             float Q[9], float p[3], float r[3], float& tau) {
    Q[0]=1.f;Q[1]=0.f;Q[2]=0.f; Q[3]=0.f;Q[4]=1.f;Q[5]=0.f; Q[6]=0.f;Q[7]=0.f;Q[8]=1.f;
    p[0]=p[1]=p[2]=0.f; r[0]=r[1]=r[2]=0.f; tau=0.f;
    #pragma unroll 1
    for (int j = 0; j < 4; j++) {
        int idx = kk + j;
        float dt = 0.f, wX = 0.f, wY = 0.f, wZ = 0.f, aX = 0.f, aY = 0.f, aZ = 0.f;
        if (idx < nsteps) {
            dt = xb[idx + 1] - xb[idx];
            wX = xb[1*T + idx]; wY = xb[2*T + idx]; wZ = xb[3*T + idx];
            aX = xb[4*T + idx]; aY = xb[5*T + idx]; aZ = xb[6*T + idx];
        }
        float ca0 = Q[0]*aX + Q[1]*aY + Q[2]*aZ;
        float ca1 = Q[3]*aX + Q[4]*aY + Q[5]*aZ;
        float ca2 = Q[6]*aX + Q[7]*aY + Q[8]*aZ;
        float hdt2 = 0.5f * dt * dt;
        r[0] += p[0]*dt + ca0*hdt2;
        r[1] += p[1]*dt + ca1*hdt2;
        r[2] += p[2]*dt + ca2*hdt2;
        p[0] += ca0*dt; p[1] += ca1*dt; p[2] += ca2*dt;
        tau  += dt;

        float px = wX*dt, py = wY*dt, pz = wZ*dt;
        float t2 = px*px + py*py + pz*pz;
        float A, Bc;
        if (t2 < 1e-8f) {
            A  = 1.0f - t2 * (1.0f/6.0f);
            Bc = 0.5f - t2 * (1.0f/24.0f);
        } else {
            float th = sqrtf(t2);
            A  = sinf(th) / th;
            Bc = (1.0f - cosf(th)) / t2;
        }
        float Bxy = Bc*px*py, Bxz = Bc*px*pz, Byz = Bc*py*pz;
        float R00 = 1.0f + Bc*(px*px - t2);
        float R11 = 1.0f + Bc*(py*py - t2);
        float R22 = 1.0f + Bc*(pz*pz - t2);
        float R01 = Bxy - A*pz, R10 = Bxy + A*pz;
        float R02 = Bxz + A*py, R20 = Bxz - A*py;
        float R12 = Byz - A*px, R21 = Byz + A*px;

        float n0 = Q[0]*R00 + Q[1]*R10 + Q[2]*R20;
        float n1 = Q[0]*R01 + Q[1]*R11 + Q[2]*R21;
        float n2 = Q[0]*R02 + Q[1]*R12 + Q[2]*R22;
        float n3 = Q[3]*R00 + Q[4]*R10 + Q[5]*R20;
        float n4 = Q[3]*R01 + Q[4]*R11 + Q[5]*R21;
        float n5 = Q[3]*R02 + Q[4]*R12 + Q[5]*R22;
        float n6 = Q[6]*R00 + Q[7]*R10 + Q[8]*R20;
        float n7 = Q[6]*R01 + Q[7]*R11 + Q[8]*R21;
        float n8 = Q[6]*R02 + Q[7]*R12 + Q[8]*R22;
        Q[0]=n0; Q[1]=n1; Q[2]=n2;
        Q[3]=n3; Q[4]=n4; Q[5]=n5;
        Q[6]=n6; Q[7]=n7; Q[8]=n8;
    }
}

// Tail-guarded float4 channel load (odd-shape path only).
__device__ __forceinline__ float4 loadc(const float* __restrict__ xb, int off, int lim) {
    float t0 = (off + 0 < lim) ? xb[off + 0] : 0.f;
    float t1 = (off + 1 < lim) ? xb[off + 1] : 0.f;
    float t2 = (off + 2 < lim) ? xb[off + 2] : 0.f;
    float t3 = (off + 3 < lim) ? xb[off + 3] : 0.f;
    return make_float4(t0, t1, t2, t3);
}

// Integrate 8 contiguous steps (lane-local), producing scalar (Q,p,r,tau).
__device__ __forceinline__ void integrate8(const float* __restrict__ xb,
                                           int k, int T, int nsteps, int lane,
                                           float Q[9], float p[3], float r[3], float& tau) {
    const bool fastld = (k + 7 < T);

    u64 DT[4];
    {
        float tv[8];
        if (fastld) {
            float4 u = *reinterpret_cast<const float4*>(xb + k);
            float4 v = *reinterpret_cast<const float4*>(xb + k + 4);
            tv[0]=u.x; tv[1]=u.y; tv[2]=u.z; tv[3]=u.w;
            tv[4]=v.x; tv[5]=v.y; tv[6]=v.z; tv[7]=v.w;
        } else {
            #pragma unroll
            for (int j = 0; j < 8; j++) tv[j] = (k + j < T) ? xb[k + j] : 0.f;
        }
        float tnext = __shfl_down_sync(0xffffffffu, tv[0], 1);
        if (lane == 31) {
            int kn = k + 8;
            tnext = (kn < T) ? xb[kn] : 0.f;
        }
        float dts[8];
        #pragma unroll
        for (int j = 0; j < 7; j++) dts[j] = tv[j + 1] - tv[j];
        dts[7] = tnext - tv[7];
        #pragma unroll
        for (int j = 0; j < 8; j++)
            if (k + j >= nsteps) dts[j] = 0.f;     // identity step
        DT[0] = pk2(dts[0], dts[4]);
        DT[1] = pk2(dts[1], dts[5]);
        DT[2] = pk2(dts[2], dts[6]);
        DT[3] = pk2(dts[3], dts[7]);
    }

    float4 wxA, wyA, wzA, axA, ayA, azA;
    float4 wxB, wyB, wzB, axB, ayB, azB;
    if (fastld) {
        wxA = *reinterpret_cast<const float4*>(xb + 1*T + k);
        wxB = *reinterpret_cast<const float4*>(xb + 1*T + k + 4);
        wyA = *reinterpret_cast<const float4*>(xb + 2*T + k);
        wyB = *reinterpret_cast<const float4*>(xb + 2*T + k + 4);
        wzA = *reinterpret_cast<const float4*>(xb + 3*T + k);
        wzB = *reinterpret_cast<const float4*>(xb + 3*T + k + 4);
        axA = *reinterpret_cast<const float4*>(xb + 4*T + k);
        axB = *reinterpret_cast<const float4*>(xb + 4*T + k + 4);
        ayA = *reinterpret_cast<const float4*>(xb + 5*T + k);
        ayB = *reinterpret_cast<const float4*>(xb + 5*T + k + 4);
        azA = *reinterpret_cast<const float4*>(xb + 6*T + k);
        azB = *reinterpret_cast<const float4*>(xb + 6*T + k + 4);
    } else {
        wxA = loadc(xb, 1*T + k, 2*T); wxB = loadc(xb, 1*T + k + 4, 2*T);
        wyA = loadc(xb, 2*T + k, 3*T); wyB = loadc(xb, 2*T + k + 4, 3*T);
        wzA = loadc(xb, 3*T + k, 4*T); wzB = loadc(xb, 3*T + k + 4, 4*T);
        axA = loadc(xb, 4*T + k, 5*T); axB = loadc(xb, 4*T + k + 4, 5*T);
        ayA = loadc(xb, 5*T + k, 6*T); ayB = loadc(xb, 5*T + k + 4, 6*T);
        azA = loadc(xb, 6*T + k, 7*T); azB = loadc(xb, 6*T + k + 4, 7*T);
    }

    u64 acc = 0ULL;
    u64 PQ[9], PP[3], PR[3], PT;
    pstep0(PQ, PP, PR, PT, DT[0],
           pk2(axA.x, axB.x), pk2(ayA.x, ayB.x), pk2(azA.x, azB.x),
           pk2(wxA.x, wxB.x), pk2(wyA.x, wyB.x), pk2(wzA.x, wzB.x), acc);
    pstep (PQ, PP, PR, PT, DT[1],
           pk2(axA.y, axB.y), pk2(ayA.y, ayB.y), pk2(azA.y, azB.y),
           pk2(wxA.y, wxB.y), pk2(wyA.y, wyB.y), pk2(wzA.y, wzB.y), acc);
    pstep (PQ, PP, PR, PT, DT[2],
           pk2(axA.z, axB.z), pk2(ayA.z, ayB.z), pk2(azA.z, azB.z),
           pk2(wxA.z, wxB.z), pk2(wyA.z, wyB.z), pk2(wzA.z, wzB.z), acc);
    pstep (PQ, PP, PR, PT, DT[3],
           pk2(axA.w, axB.w), pk2(ayA.w, ayB.w), pk2(azA.w, azB.w),
           pk2(wxA.w, wxB.w), pk2(wyA.w, wyB.w), pk2(wzA.w, wzB.w), acc);

    float QB[9], pB[3], rB[3], tauB;
    #pragma unroll
    for (int i = 0; i < 9; i++) up2(PQ[i], Q[i], QB[i]);
    #pragma unroll
    for (int i = 0; i < 3; i++) { up2(PP[i], p[i], pB[i]); up2(PR[i], r[i], rB[i]); }
    up2(PT, tau, tauB);

    {
        float mlo, mhi; up2(acc, mlo, mhi);
        if (__builtin_expect(fmaxf(mlo, mhi) > 0.0625f, 0)) {
            exact_chain4(xb, k,     T, nsteps, Q,  p,  r,  tau);
            exact_chain4(xb, k + 4, T, nsteps, QB, pB, rB, tauB);
        }
    }
    compose(Q, p, r, tau, QB, pB, rB, tauB);
}

__global__ __launch_bounds__(128, 5)
void rmi_kernel(const float* __restrict__ x, float* __restrict__ out,
                int T, int chunk)
{
    const int b    = blockIdx.x;
    const int warp = threadIdx.x >> 5;
    const int lane = threadIdx.x & 31;
    const int nsteps = T - 1;

    const float* xb = x + (size_t)b * 7 * (size_t)T;
    const int rounds = chunk >> 8;

    __shared__ float seg[32][16];

    if (rounds == 1) {
        // ---- fast path: 1024 steps total, 2-stage partial tree ----
        float Q[9], p[3], r[3], tau;
        integrate8(xb, warp * 256 + lane * 8, T, nsteps, lane, Q, p, r, tau);

        tree_stage(Q, p, r, tau, 1);   // lane l: [8l, 8l+16)
        tree_stage(Q, p, r, tau, 2);   // lane l: [8l, 8l+32)

        if ((lane & 3) == 0) {
            int j = warp * 8 + (lane >> 2);     // ordered segment index
            float* s = seg[j];
            #pragma unroll
            for (int i = 0; i < 9; i++) s[i] = Q[i];
            s[9]  = p[0]; s[10] = p[1]; s[11] = p[2];
            s[12] = r[0]; s[13] = r[1]; s[14] = r[2];
            s[15] = tau;
        }
        __syncthreads();

        if (warp == 0) {
            float FQ[9], Fp[3], Fr[3], Ftau;
            const float* s = seg[lane];
            #pragma unroll
            for (int i = 0; i < 9; i++) FQ[i] = s[i];
            Fp[0]=s[9];  Fp[1]=s[10]; Fp[2]=s[11];
            Fr[0]=s[12]; Fr[1]=s[13]; Fr[2]=s[14];
            Ftau = s[15];

            #pragma unroll
            for (int off = 1; off < 32; off <<= 1)
                tree_stage(FQ, Fp, Fr, Ftau, off);

            if (lane == 0) {
                float* o = out + (size_t)b * 15;
                #pragma unroll
                for (int i = 0; i < 9; i++) o[i] = FQ[i];
                o[9]  = Fp[0]; o[10] = Fp[1]; o[11] = Fp[2];
                o[12] = Fr[0]; o[13] = Fr[1]; o[14] = Fr[2];
            }
        }
    } else {
        // ---- generic path (rounds > 1): full tree per round ----
        float TQ[9], Tp[3], Tr[3], Ttau;
        {
            float Q[9], p[3], r[3], tau;
            integrate8(xb, warp * chunk + lane * 8, T, nsteps, lane, Q, p, r, tau);
            #pragma unroll
            for (int off = 1; off < 32; off <<= 1) tree_stage(Q, p, r, tau, off);
            #pragma unroll
            for (int i = 0; i < 9; i++) TQ[i] = Q[i];
            #pragma unroll
            for (int i = 0; i < 3; i++) { Tp[i] = p[i]; Tr[i] = r[i]; }
            Ttau = tau;
        }
        for (int rr = 1; rr < rounds; rr++) {
            float Q[9], p[3], r[3], tau;
            integrate8(xb, warp * chunk + rr * 256 + lane * 8, T, nsteps, lane,
                       Q, p, r, tau);
            #pragma unroll
            for (int off = 1; off < 32; off <<= 1) tree_stage(Q, p, r, tau, off);
            compose(TQ, Tp, Tr, Ttau, Q, p, r, tau);
        }

        if (lane == 0) {
            float* s = seg[warp];
            #pragma unroll
            for (int i = 0; i < 9; i++) s[i] = TQ[i];
            s[9]  = Tp[0]; s[10] = Tp[1]; s[11] = Tp[2];
            s[12] = Tr[0]; s[13] = Tr[1]; s[14] = Tr[2];
            s[15] = Ttau;
        }
        __syncthreads();

        if (warp == 0 && lane == 0) {
            float FQ[9], Fp[3], Fr[3], Ftau;
            #pragma unroll
            for (int i = 0; i < 9; i++) FQ[i] = seg[0][i];
            Fp[0]=seg[0][9];  Fp[1]=seg[0][10]; Fp[2]=seg[0][11];
            Fr[0]=seg[0][12]; Fr[1]=seg[0][13]; Fr[2]=seg[0][14];
            Ftau = seg[0][15];
            #pragma unroll
            for (int wsg = 1; wsg < 4; wsg++) {
                float Q2[9], p2[3], r2[3], tau2;
                #pragma unroll
                for (int i = 0; i < 9; i++) Q2[i] = seg[wsg][i];
                p2[0]=seg[wsg][9];  p2[1]=seg[wsg][10]; p2[2]=seg[wsg][11];
                r2[0]=seg[wsg][12]; r2[1]=seg[wsg][13]; r2[2]=seg[wsg][14];
                tau2 = seg[wsg][15];
                compose(FQ, Fp, Fr, Ftau, Q2, p2, r2, tau2);
            }
            float* o = out + (size_t)b * 15;
            #pragma unroll
            for (int i = 0; i < 9; i++) o[i] = FQ[i];
            o[9]  = Fp[0]; o[10] = Fp[1]; o[11] = Fp[2];
            o[12] = Fr[0]; o[13] = Fr[1]; o[14] = Fr[2];
        }
    }
}

extern "C" void kernel_launch(void* const* d_in, const int* in_sizes, int n_in,
                              void* d_out, int out_size) {
    const float* x = (const float*)d_in[0];
    float* out = (float*)d_out;

    int B = out_size / 15;
    int T = in_sizes[0] / (7 * B);
    int nsteps = T - 1;

    // per-warp contiguous chunk, multiple of 256, 4 warps cover all steps
    int chunk = ((nsteps + 1023) / 1024) * 256;

    rmi_kernel<<<B, 128>>>(x, out, T, chunk);
}